// round 1
// baseline (speedup 1.0000x reference)
#include <cuda_runtime.h>
#include <cuda_bf16.h>
#include <math.h>

// ---------------- Problem constants (fixed shapes) ----------------
#define SEQ       65536
#define EMBED     1280
#define NECK      320
#define QKVD      960      // 3 * NECK
#define NHEAD     4
#define HDIM      80
#define S1C       256
#define TC        256

// ---------------- Scratch (alloc-free: __device__ globals) --------
__device__ float g_qkv[(size_t)SEQ * QKVD];   // [t*S1+s, 960]
__device__ float g_att[(size_t)SEQ * NECK];   // [s*T+t, 320]

// ---------------- SGEMM: C[M,N] = A[M,K] @ B[N,K]^T + bias[N] -----
// 128x128 tile, BK=8, 256 threads, 8x8 per thread.
#define BM 128
#define BN 128
#define BK 8
#define TM 8
#define TN 8

__global__ __launch_bounds__(256)
void sgemm_tn_bias(const float* __restrict__ A,
                   const float* __restrict__ B,
                   const float* __restrict__ bias,
                   float* __restrict__ C,
                   int M, int N, int K)
{
    __shared__ float As[BK][BM];
    __shared__ float Bs[BK][BN];

    const int tid = threadIdx.x;
    const int bm  = blockIdx.y * BM;
    const int bn  = blockIdx.x * BN;

    const int lr = tid >> 1;          // 0..127 : row within tile
    const int lc = (tid & 1) * 4;     // 0 or 4 : col (float4)

    const int ty = tid >> 4;          // 0..15
    const int tx = tid & 15;          // 0..15

    float acc[TM][TN];
    #pragma unroll
    for (int i = 0; i < TM; i++)
        #pragma unroll
        for (int j = 0; j < TN; j++)
            acc[i][j] = 0.f;

    for (int k0 = 0; k0 < K; k0 += BK) {
        float4 a4 = make_float4(0.f, 0.f, 0.f, 0.f);
        float4 b4 = make_float4(0.f, 0.f, 0.f, 0.f);
        if (bm + lr < M)
            a4 = *(const float4*)(A + (size_t)(bm + lr) * K + k0 + lc);
        if (bn + lr < N)
            b4 = *(const float4*)(B + (size_t)(bn + lr) * K + k0 + lc);

        __syncthreads();   // protect previous iteration's smem reads
        As[lc + 0][lr] = a4.x; As[lc + 1][lr] = a4.y;
        As[lc + 2][lr] = a4.z; As[lc + 3][lr] = a4.w;
        Bs[lc + 0][lr] = b4.x; Bs[lc + 1][lr] = b4.y;
        Bs[lc + 2][lr] = b4.z; Bs[lc + 3][lr] = b4.w;
        __syncthreads();

        #pragma unroll
        for (int kk = 0; kk < BK; kk++) {
            float a[TM], b[TN];
            #pragma unroll
            for (int i = 0; i < TM; i++) a[i] = As[kk][ty * TM + i];
            #pragma unroll
            for (int j = 0; j < TN; j++) b[j] = Bs[kk][tx * TN + j];
            #pragma unroll
            for (int i = 0; i < TM; i++)
                #pragma unroll
                for (int j = 0; j < TN; j++)
                    acc[i][j] = fmaf(a[i], b[j], acc[i][j]);
        }
    }

    #pragma unroll
    for (int i = 0; i < TM; i++) {
        const int m = bm + ty * TM + i;
        if (m >= M) continue;
        #pragma unroll
        for (int j = 0; j < TN; j++) {
            const int n = bn + tx * TN + j;
            if (n < N)
                C[(size_t)m * N + n] = acc[i][j] + bias[n];
        }
    }
}

// ---------------- Attention kernel --------------------------------
// grid = (S1, H), 256 threads; thread tid == query index t_q.
// qkv row r = t*S1 + s, layout [r, c*NECK + h*HDIM + d].
// Output row = s*T + t, col = h*HDIM + d.
// K and V tiles in smem (2 * 256*80*4 = 160 KB). RoPE applied in-place.
__global__ __launch_bounds__(256)
void attn_kernel(const float* __restrict__ qkv,
                 const float* __restrict__ freqs,   // [T, 40]
                 float* __restrict__ attout)
{
    extern __shared__ float sh[];
    float* sk = sh;                 // [T][HDIM]
    float* sv = sh + TC * HDIM;     // [T][HDIM]

    const int s   = blockIdx.x;
    const int h   = blockIdx.y;
    const int tid = threadIdx.x;
    const size_t base = (size_t)h * HDIM;

    // ---- load K (raw) ----
    for (int idx = tid; idx < TC * HDIM; idx += 256) {
        const int t = idx / HDIM, d = idx % HDIM;
        sk[idx] = qkv[(size_t)(t * S1C + s) * QKVD + NECK + base + d];
    }
    __syncthreads();
    // ---- RoPE K in place ----
    for (int idx = tid; idx < TC * (HDIM / 2); idx += 256) {
        const int t = idx / (HDIM / 2), j = idx % (HDIM / 2);
        const float f  = freqs[t * (HDIM / 2) + j];
        const float c  = cosf(f), sn = sinf(f);
        const float x1 = sk[t * HDIM + j];
        const float x2 = sk[t * HDIM + j + HDIM / 2];
        sk[t * HDIM + j]            = x1 * c - x2 * sn;
        sk[t * HDIM + j + HDIM / 2] = x2 * c + x1 * sn;
    }
    __syncthreads();

    // ---- load Q (raw) into sv, RoPE, copy own row to regs ----
    for (int idx = tid; idx < TC * HDIM; idx += 256) {
        const int t = idx / HDIM, d = idx % HDIM;
        sv[idx] = qkv[(size_t)(t * S1C + s) * QKVD + base + d];
    }
    __syncthreads();
    for (int idx = tid; idx < TC * (HDIM / 2); idx += 256) {
        const int t = idx / (HDIM / 2), j = idx % (HDIM / 2);
        const float f  = freqs[t * (HDIM / 2) + j];
        const float c  = cosf(f), sn = sinf(f);
        const float x1 = sv[t * HDIM + j];
        const float x2 = sv[t * HDIM + j + HDIM / 2];
        sv[t * HDIM + j]            = x1 * c - x2 * sn;
        sv[t * HDIM + j + HDIM / 2] = x2 * c + x1 * sn;
    }
    __syncthreads();

    float q[HDIM];
    #pragma unroll
    for (int d = 0; d < HDIM; d++) q[d] = sv[tid * HDIM + d];
    __syncthreads();

    // ---- load V into sv ----
    for (int idx = tid; idx < TC * HDIM; idx += 256) {
        const int t = idx / HDIM, d = idx % HDIM;
        sv[idx] = qkv[(size_t)(t * S1C + s) * QKVD + 2 * NECK + base + d];
    }
    __syncthreads();

    const float scale = 0.111803398874989484f;   // 1/sqrt(80)

    // ---- pass 1: online max / sum ----
    float m = -1e30f, l = 0.f;
    for (int tk = 0; tk < TC; tk++) {
        const float* kr = sk + tk * HDIM;
        float sdot = 0.f;
        #pragma unroll
        for (int d = 0; d < HDIM; d++) sdot = fmaf(q[d], kr[d], sdot);
        sdot *= scale;
        const float mn = fmaxf(m, sdot);
        l = l * __expf(m - mn) + __expf(sdot - mn);
        m = mn;
    }
    const float rl = 1.f / l;

    // ---- pass 2: weighted V accumulate ----
    float acc[HDIM];
    #pragma unroll
    for (int d = 0; d < HDIM; d++) acc[d] = 0.f;
    for (int tk = 0; tk < TC; tk++) {
        const float* kr = sk + tk * HDIM;
        float sdot = 0.f;
        #pragma unroll
        for (int d = 0; d < HDIM; d++) sdot = fmaf(q[d], kr[d], sdot);
        const float p = __expf(sdot * scale - m) * rl;
        const float* vr = sv + tk * HDIM;
        #pragma unroll
        for (int d = 0; d < HDIM; d++) acc[d] = fmaf(p, vr[d], acc[d]);
    }

    // ---- stage through smem for coalesced store ----
    __syncthreads();
    #pragma unroll
    for (int d = 0; d < HDIM; d++) sk[tid * HDIM + d] = acc[d];
    __syncthreads();
    for (int idx = tid; idx < TC * HDIM; idx += 256) {
        const int t = idx / HDIM, d = idx % HDIM;
        attout[(size_t)(s * TC + t) * NECK + base + d] = sk[idx];
    }
}

// ---------------- Launch -------------------------------------------
extern "C" void kernel_launch(void* const* d_in, const int* in_sizes, int n_in,
                              void* d_out, int out_size)
{
    const float* hidden = (const float*)d_in[0];
    // d_in[1] = cu_seqlens (shapes fixed; unused)
    const float* freqs  = (const float*)d_in[2];
    const float* w_qkv  = (const float*)d_in[3];
    const float* b_qkv  = (const float*)d_in[4];
    const float* w_proj = (const float*)d_in[5];
    const float* b_proj = (const float*)d_in[6];
    float* out = (float*)d_out;

    float *qkv_ptr = nullptr, *att_ptr = nullptr;
    cudaGetSymbolAddress((void**)&qkv_ptr, g_qkv);
    cudaGetSymbolAddress((void**)&att_ptr, g_att);

    // 1) QKV GEMM: [65536,960] = hidden @ w_qkv^T + b_qkv
    {
        dim3 grid((QKVD + BN - 1) / BN, SEQ / BM);
        sgemm_tn_bias<<<grid, 256>>>(hidden, w_qkv, b_qkv, qkv_ptr,
                                     SEQ, QKVD, EMBED);
    }

    // 2) Attention (RoPE fused)
    {
        const int smem = 2 * TC * HDIM * (int)sizeof(float);   // 163840
        cudaFuncSetAttribute(attn_kernel,
                             cudaFuncAttributeMaxDynamicSharedMemorySize, smem);
        dim3 grid(S1C, NHEAD);
        attn_kernel<<<grid, 256, smem>>>(qkv_ptr, freqs, att_ptr);
    }

    // 3) Proj GEMM: out[65536,1280] = att @ w_proj^T + b_proj
    {
        dim3 grid(EMBED / BN, SEQ / BM);
        sgemm_tn_bias<<<grid, 256>>>(att_ptr, w_proj, b_proj, out,
                                     SEQ, EMBED, NECK);
    }
}

// round 2
// speedup vs baseline: 2.2097x; 2.2097x over previous
#include <cuda_runtime.h>
#include <cuda_bf16.h>
#include <math.h>
#include <stdint.h>

// ---------------- Problem constants (fixed shapes) ----------------
#define SEQ       65536
#define EMBED     1280
#define NECK      320
#define QKVD      960      // 3 * NECK
#define NHEAD     4
#define HDIM      80
#define S1C       256
#define TC        256

// ---------------- Scratch (alloc-free: __device__ globals) --------
__device__ float g_qkv[(size_t)SEQ * QKVD];   // [t*S1+s, 960]
__device__ float g_att[(size_t)SEQ * NECK];   // [s*T+t, 320]

// ================= TF32 tensor-core GEMM ==========================
// C[M,N] = A[M,K] @ B[N,K]^T + bias[N]
// Block 128x128, BK=16, 256 threads (8 warps), warp tile 64x32,
// mma.sync.m16n8k8.tf32, fp32 accumulate. Double-buffered smem.
//
// Smem layout (both A and B tiles, [128 rows][16 k]):
//   phys(r, k) = r*16 + 4*((k&3) ^ (r&3)) + (k>>2)
// -> thread t4=k&3 reads its whole k-fragment {t4, t4+4, t4+8, t4+12}
//    for row r as ONE float4 at col 4*(t4 ^ (r&3)); conflict-free.

__device__ __forceinline__ float to_tf32(float x) {
    uint32_t u;
    asm("cvt.rna.tf32.f32 %0, %1;" : "=r"(u) : "f"(x));
    return __uint_as_float(u);
}

__device__ __forceinline__ void mma_tf32(float4& d,
    uint32_t a0, uint32_t a1, uint32_t a2, uint32_t a3,
    uint32_t b0, uint32_t b1)
{
    asm volatile(
        "mma.sync.aligned.m16n8k8.row.col.f32.tf32.tf32.f32 "
        "{%0,%1,%2,%3}, {%4,%5,%6,%7}, {%8,%9}, {%0,%1,%2,%3};\n"
        : "+f"(d.x), "+f"(d.y), "+f"(d.z), "+f"(d.w)
        : "r"(a0), "r"(a1), "r"(a2), "r"(a3), "r"(b0), "r"(b1));
}

__global__ __launch_bounds__(256)
void gemm_tf32_tn_bias(const float* __restrict__ A,
                       const float* __restrict__ B,
                       const float* __restrict__ bias,
                       float* __restrict__ C,
                       int M, int N, int K)
{
    __shared__ float As[2][128 * 16];
    __shared__ float Bs[2][128 * 16];

    const int tid  = threadIdx.x;
    const int lane = tid & 31;
    const int warp = tid >> 5;
    const int wm   = warp >> 2;      // 0..1
    const int wn   = warp & 3;       // 0..3
    const int g    = lane >> 2;      // groupID 0..7
    const int t4   = lane & 3;       // threadID in group
    const int sw   = ((t4 ^ (g & 3)) << 2);

    const int bm = blockIdx.y * 128;
    const int bn = blockIdx.x * 128;

    const int r0 = tid >> 2;         // 0..63 (load row, i=0)
    const int jc = tid & 3;          // float4 column within row

    float4 ra[2], rb[2];
    float4 acc[4][4];
    #pragma unroll
    for (int i = 0; i < 4; i++)
        #pragma unroll
        for (int j = 0; j < 4; j++)
            acc[i][j] = make_float4(0.f, 0.f, 0.f, 0.f);

    const int KT = K >> 4;

    // -------- prologue: load + store tile 0 --------
    #pragma unroll
    for (int i = 0; i < 2; i++) {
        int r = r0 + 64 * i;
        ra[i] = *(const float4*)(A + (size_t)(bm + r) * K + 4 * jc);
        rb[i] = (bn + r < N)
              ? *(const float4*)(B + (size_t)(bn + r) * K + 4 * jc)
              : make_float4(0.f, 0.f, 0.f, 0.f);
    }
    #pragma unroll
    for (int i = 0; i < 2; i++) {
        int r = r0 + 64 * i;
        float* pa = &As[0][r * 16];
        float* pb = &Bs[0][r * 16];
        int s0 = ((0 ^ (r & 3)) << 2) + jc;
        int s1 = ((1 ^ (r & 3)) << 2) + jc;
        int s2 = ((2 ^ (r & 3)) << 2) + jc;
        int s3 = ((3 ^ (r & 3)) << 2) + jc;
        pa[s0] = to_tf32(ra[i].x); pa[s1] = to_tf32(ra[i].y);
        pa[s2] = to_tf32(ra[i].z); pa[s3] = to_tf32(ra[i].w);
        pb[s0] = to_tf32(rb[i].x); pb[s1] = to_tf32(rb[i].y);
        pb[s2] = to_tf32(rb[i].z); pb[s3] = to_tf32(rb[i].w);
    }
    __syncthreads();

    // -------- mainloop --------
    for (int kt = 0; kt < KT; kt++) {
        const int buf = kt & 1;

        if (kt + 1 < KT) {
            const int k0 = (kt + 1) << 4;
            #pragma unroll
            for (int i = 0; i < 2; i++) {
                int r = r0 + 64 * i;
                ra[i] = *(const float4*)(A + (size_t)(bm + r) * K + k0 + 4 * jc);
                rb[i] = (bn + r < N)
                      ? *(const float4*)(B + (size_t)(bn + r) * K + k0 + 4 * jc)
                      : make_float4(0.f, 0.f, 0.f, 0.f);
            }
        }

        // fragment loads (conflict-free LDS.128)
        float4 fa[4], fa2[4], fb[4];
        const float* pa = &As[buf][(wm * 64 + g) * 16 + sw];
        const float* pb = &Bs[buf][(wn * 32 + g) * 16 + sw];
        #pragma unroll
        for (int mt = 0; mt < 4; mt++) {
            fa[mt]  = *(const float4*)(pa + mt * 256);
            fa2[mt] = *(const float4*)(pa + mt * 256 + 128);
        }
        #pragma unroll
        for (int nt = 0; nt < 4; nt++)
            fb[nt] = *(const float4*)(pb + nt * 128);

        #pragma unroll
        for (int mt = 0; mt < 4; mt++)
            #pragma unroll
            for (int nt = 0; nt < 4; nt++) {
                mma_tf32(acc[mt][nt],
                         __float_as_uint(fa[mt].x), __float_as_uint(fa2[mt].x),
                         __float_as_uint(fa[mt].y), __float_as_uint(fa2[mt].y),
                         __float_as_uint(fb[nt].x), __float_as_uint(fb[nt].y));
                mma_tf32(acc[mt][nt],
                         __float_as_uint(fa[mt].z), __float_as_uint(fa2[mt].z),
                         __float_as_uint(fa[mt].w), __float_as_uint(fa2[mt].w),
                         __float_as_uint(fb[nt].z), __float_as_uint(fb[nt].w));
            }

        if (kt + 1 < KT) {
            const int nb = buf ^ 1;
            #pragma unroll
            for (int i = 0; i < 2; i++) {
                int r = r0 + 64 * i;
                float* qa = &As[nb][r * 16];
                float* qb = &Bs[nb][r * 16];
                int s0 = ((0 ^ (r & 3)) << 2) + jc;
                int s1 = ((1 ^ (r & 3)) << 2) + jc;
                int s2 = ((2 ^ (r & 3)) << 2) + jc;
                int s3 = ((3 ^ (r & 3)) << 2) + jc;
                qa[s0] = to_tf32(ra[i].x); qa[s1] = to_tf32(ra[i].y);
                qa[s2] = to_tf32(ra[i].z); qa[s3] = to_tf32(ra[i].w);
                qb[s0] = to_tf32(rb[i].x); qb[s1] = to_tf32(rb[i].y);
                qb[s2] = to_tf32(rb[i].z); qb[s3] = to_tf32(rb[i].w);
            }
            __syncthreads();
        }
    }

    // -------- epilogue: bias + store --------
    #pragma unroll
    for (int mt = 0; mt < 4; mt++) {
        const int row = bm + wm * 64 + mt * 16 + g;
        #pragma unroll
        for (int nt = 0; nt < 4; nt++) {
            const int col = bn + wn * 32 + nt * 8 + 2 * t4;
            if (col < N) {
                const float bx = bias[col], by = bias[col + 1];
                float2 v0 = make_float2(acc[mt][nt].x + bx, acc[mt][nt].y + by);
                float2 v1 = make_float2(acc[mt][nt].z + bx, acc[mt][nt].w + by);
                *(float2*)(C + (size_t)row * N + col)       = v0;
                *(float2*)(C + (size_t)(row + 8) * N + col) = v1;
            }
        }
    }
}

// ---------------- Attention kernel (fp32, unchanged) --------------
__global__ __launch_bounds__(256)
void attn_kernel(const float* __restrict__ qkv,
                 const float* __restrict__ freqs,   // [T, 40]
                 float* __restrict__ attout)
{
    extern __shared__ float sh[];
    float* sk = sh;                 // [T][HDIM]
    float* sv = sh + TC * HDIM;     // [T][HDIM]

    const int s   = blockIdx.x;
    const int h   = blockIdx.y;
    const int tid = threadIdx.x;
    const size_t base = (size_t)h * HDIM;

    for (int idx = tid; idx < TC * HDIM; idx += 256) {
        const int t = idx / HDIM, d = idx % HDIM;
        sk[idx] = qkv[(size_t)(t * S1C + s) * QKVD + NECK + base + d];
    }
    __syncthreads();
    for (int idx = tid; idx < TC * (HDIM / 2); idx += 256) {
        const int t = idx / (HDIM / 2), j = idx % (HDIM / 2);
        const float f  = freqs[t * (HDIM / 2) + j];
        const float c  = cosf(f), sn = sinf(f);
        const float x1 = sk[t * HDIM + j];
        const float x2 = sk[t * HDIM + j + HDIM / 2];
        sk[t * HDIM + j]            = x1 * c - x2 * sn;
        sk[t * HDIM + j + HDIM / 2] = x2 * c + x1 * sn;
    }
    __syncthreads();

    for (int idx = tid; idx < TC * HDIM; idx += 256) {
        const int t = idx / HDIM, d = idx % HDIM;
        sv[idx] = qkv[(size_t)(t * S1C + s) * QKVD + base + d];
    }
    __syncthreads();
    for (int idx = tid; idx < TC * (HDIM / 2); idx += 256) {
        const int t = idx / (HDIM / 2), j = idx % (HDIM / 2);
        const float f  = freqs[t * (HDIM / 2) + j];
        const float c  = cosf(f), sn = sinf(f);
        const float x1 = sv[t * HDIM + j];
        const float x2 = sv[t * HDIM + j + HDIM / 2];
        sv[t * HDIM + j]            = x1 * c - x2 * sn;
        sv[t * HDIM + j + HDIM / 2] = x2 * c + x1 * sn;
    }
    __syncthreads();

    float q[HDIM];
    #pragma unroll
    for (int d = 0; d < HDIM; d++) q[d] = sv[tid * HDIM + d];
    __syncthreads();

    for (int idx = tid; idx < TC * HDIM; idx += 256) {
        const int t = idx / HDIM, d = idx % HDIM;
        sv[idx] = qkv[(size_t)(t * S1C + s) * QKVD + 2 * NECK + base + d];
    }
    __syncthreads();

    const float scale = 0.111803398874989484f;   // 1/sqrt(80)

    float m = -1e30f, l = 0.f;
    for (int tk = 0; tk < TC; tk++) {
        const float* kr = sk + tk * HDIM;
        float sdot = 0.f;
        #pragma unroll
        for (int d = 0; d < HDIM; d++) sdot = fmaf(q[d], kr[d], sdot);
        sdot *= scale;
        const float mn = fmaxf(m, sdot);
        l = l * __expf(m - mn) + __expf(sdot - mn);
        m = mn;
    }
    const float rl = 1.f / l;

    float acc[HDIM];
    #pragma unroll
    for (int d = 0; d < HDIM; d++) acc[d] = 0.f;
    for (int tk = 0; tk < TC; tk++) {
        const float* kr = sk + tk * HDIM;
        float sdot = 0.f;
        #pragma unroll
        for (int d = 0; d < HDIM; d++) sdot = fmaf(q[d], kr[d], sdot);
        const float p = __expf(sdot * scale - m) * rl;
        const float* vr = sv + tk * HDIM;
        #pragma unroll
        for (int d = 0; d < HDIM; d++) acc[d] = fmaf(p, vr[d], acc[d]);
    }

    __syncthreads();
    #pragma unroll
    for (int d = 0; d < HDIM; d++) sk[tid * HDIM + d] = acc[d];
    __syncthreads();
    for (int idx = tid; idx < TC * HDIM; idx += 256) {
        const int t = idx / HDIM, d = idx % HDIM;
        attout[(size_t)(s * TC + t) * NECK + base + d] = sk[idx];
    }
}

// ---------------- Launch -------------------------------------------
extern "C" void kernel_launch(void* const* d_in, const int* in_sizes, int n_in,
                              void* d_out, int out_size)
{
    const float* hidden = (const float*)d_in[0];
    // d_in[1] = cu_seqlens (shapes fixed; unused)
    const float* freqs  = (const float*)d_in[2];
    const float* w_qkv  = (const float*)d_in[3];
    const float* b_qkv  = (const float*)d_in[4];
    const float* w_proj = (const float*)d_in[5];
    const float* b_proj = (const float*)d_in[6];
    float* out = (float*)d_out;

    float *qkv_ptr = nullptr, *att_ptr = nullptr;
    cudaGetSymbolAddress((void**)&qkv_ptr, g_qkv);
    cudaGetSymbolAddress((void**)&att_ptr, g_att);

    // 1) QKV GEMM: [65536,960] = hidden @ w_qkv^T + b_qkv   (K=1280)
    {
        dim3 grid((QKVD + 127) / 128, SEQ / 128);
        gemm_tf32_tn_bias<<<grid, 256>>>(hidden, w_qkv, b_qkv, qkv_ptr,
                                         SEQ, QKVD, EMBED);
    }

    // 2) Attention (RoPE fused)
    {
        const int smem = 2 * TC * HDIM * (int)sizeof(float);   // 163840
        cudaFuncSetAttribute(attn_kernel,
                             cudaFuncAttributeMaxDynamicSharedMemorySize, smem);
        dim3 grid(S1C, NHEAD);
        attn_kernel<<<grid, 256, smem>>>(qkv_ptr, freqs, att_ptr);
    }

    // 3) Proj GEMM: out[65536,1280] = att @ w_proj^T + b_proj  (K=320)
    {
        dim3 grid(EMBED / 128, SEQ / 128);
        gemm_tf32_tn_bias<<<grid, 256>>>(att_ptr, w_proj, b_proj, out,
                                         SEQ, EMBED, NECK);
    }
}

// round 4
// speedup vs baseline: 2.2404x; 1.0139x over previous
#include <cuda_runtime.h>
#include <cuda_bf16.h>
#include <math.h>
#include <stdint.h>

// ---------------- Problem constants (fixed shapes) ----------------
#define SEQ       65536
#define EMBED     1280
#define NECK      320
#define QKVD      960      // 3 * NECK
#define NHEAD     4
#define HDIM      80
#define S1C       256
#define TC        256

// ---------------- Scratch (alloc-free: __device__ globals) --------
__device__ float g_qkv[(size_t)SEQ * QKVD];     // [t*S1+s, 960]
__device__ float g_att[(size_t)SEQ * NECK];     // [s*T+t, 320] (tf32-rounded)
__device__ float g_hid[(size_t)SEQ * EMBED];    // tf32-rounded hidden
__device__ float g_wqkv[(size_t)QKVD * EMBED];  // tf32-rounded w_qkv
__device__ float g_wproj[(size_t)EMBED * NECK]; // tf32-rounded w_proj

// ================= helpers ========================================
__device__ __forceinline__ float to_tf32(float x) {
    uint32_t u;
    asm("cvt.rna.tf32.f32 %0, %1;" : "=r"(u) : "f"(x));
    return __uint_as_float(u);
}

__device__ __forceinline__ void mma_tf32(float4& d,
    float a0, float a1, float a2, float a3, float b0, float b1)
{
    asm volatile(
        "mma.sync.aligned.m16n8k8.row.col.f32.tf32.tf32.f32 "
        "{%0,%1,%2,%3}, {%4,%5,%6,%7}, {%8,%9}, {%0,%1,%2,%3};\n"
        : "+f"(d.x), "+f"(d.y), "+f"(d.z), "+f"(d.w)
        : "r"(__float_as_uint(a0)), "r"(__float_as_uint(a1)),
          "r"(__float_as_uint(a2)), "r"(__float_as_uint(a3)),
          "r"(__float_as_uint(b0)), "r"(__float_as_uint(b1)));
}

// ================= TF32 tensor-core GEMM ==========================
// C[M,N] = A[M,K] @ B[N,K]^T + bias[N]; A,B already tf32-rounded.
// Block 128x256, BK=16, 256 threads (8 warps), warp tile 64x64.
// Smem layout per tile row r (16 k-floats):
//   phys(r,k) = r*16 + 4*((k&3)^(r&3)) + (k>>2)
// Thread (g,t4) reads its k-fragment {t4,t4+4,t4+8,t4+12} for row r as
// one float4 at col 4*(t4^(r&3)).

__global__ __launch_bounds__(256, 1)
void gemm_tf32_tn_bias(const float* __restrict__ A,
                       const float* __restrict__ B,
                       const float* __restrict__ bias,
                       float* __restrict__ C,
                       int M, int N, int K)
{
    __shared__ float As[2][128 * 16];
    __shared__ float Bs[2][256 * 16];

    const int tid  = threadIdx.x;
    const int lane = tid & 31;
    const int warp = tid >> 5;
    const int wm   = warp >> 2;      // 0..1 (64 M-rows each)
    const int wn   = warp & 3;       // 0..3 (64 N-cols each)
    const int g    = lane >> 2;      // 0..7
    const int t4   = lane & 3;       // 0..3
    const int sw   = ((t4 ^ (g & 3)) << 2);

    const int bm = blockIdx.y * 128;
    const int bn = blockIdx.x * 256;

    const int r4 = tid >> 2;         // 0..63 (base load row)
    const int jc = tid & 3;          // float4 column within row

    float4 ra[2], rb[4];
    float4 acc[4][8];
    #pragma unroll
    for (int i = 0; i < 4; i++)
        #pragma unroll
        for (int j = 0; j < 8; j++)
            acc[i][j] = make_float4(0.f, 0.f, 0.f, 0.f);

    const int KT = K >> 4;

    // -------- prologue: load + store tile 0 --------
    #pragma unroll
    for (int i = 0; i < 2; i++)
        ra[i] = *(const float4*)(A + (size_t)(bm + r4 + 64 * i) * K + 4 * jc);
    #pragma unroll
    for (int i = 0; i < 4; i++) {
        const int r = r4 + 64 * i;
        rb[i] = (bn + r < N)
              ? *(const float4*)(B + (size_t)(bn + r) * K + 4 * jc)
              : make_float4(0.f, 0.f, 0.f, 0.f);
    }
    #pragma unroll
    for (int i = 0; i < 2; i++) {
        const int r = r4 + 64 * i;
        float* p = &As[0][r * 16];
        p[((0 ^ (r & 3)) << 2) + jc] = ra[i].x;
        p[((1 ^ (r & 3)) << 2) + jc] = ra[i].y;
        p[((2 ^ (r & 3)) << 2) + jc] = ra[i].z;
        p[((3 ^ (r & 3)) << 2) + jc] = ra[i].w;
    }
    #pragma unroll
    for (int i = 0; i < 4; i++) {
        const int r = r4 + 64 * i;
        float* p = &Bs[0][r * 16];
        p[((0 ^ (r & 3)) << 2) + jc] = rb[i].x;
        p[((1 ^ (r & 3)) << 2) + jc] = rb[i].y;
        p[((2 ^ (r & 3)) << 2) + jc] = rb[i].z;
        p[((3 ^ (r & 3)) << 2) + jc] = rb[i].w;
    }
    __syncthreads();

    // -------- mainloop --------
    for (int kt = 0; kt < KT; kt++) {
        const int buf = kt & 1;

        if (kt + 1 < KT) {
            const int k0 = (kt + 1) << 4;
            #pragma unroll
            for (int i = 0; i < 2; i++)
                ra[i] = *(const float4*)(A + (size_t)(bm + r4 + 64 * i) * K + k0 + 4 * jc);
            #pragma unroll
            for (int i = 0; i < 4; i++) {
                const int r = r4 + 64 * i;
                rb[i] = (bn + r < N)
                      ? *(const float4*)(B + (size_t)(bn + r) * K + k0 + 4 * jc)
                      : make_float4(0.f, 0.f, 0.f, 0.f);
            }
        }

        const float* pa = &As[buf][(wm * 64 + g) * 16 + sw];
        const float* pb = &Bs[buf][(wn * 64 + g) * 16 + sw];

        float4 fb[8];
        #pragma unroll
        for (int nt = 0; nt < 8; nt++)
            fb[nt] = *(const float4*)(pb + nt * 128);

        #pragma unroll
        for (int mt = 0; mt < 4; mt++) {
            const float4 fa  = *(const float4*)(pa + mt * 256);
            const float4 fa2 = *(const float4*)(pa + mt * 256 + 128);
            #pragma unroll
            for (int nt = 0; nt < 8; nt++) {
                mma_tf32(acc[mt][nt], fa.x, fa2.x, fa.y, fa2.y, fb[nt].x, fb[nt].y);
                mma_tf32(acc[mt][nt], fa.z, fa2.z, fa.w, fa2.w, fb[nt].z, fb[nt].w);
            }
        }

        if (kt + 1 < KT) {
            const int nb = buf ^ 1;
            #pragma unroll
            for (int i = 0; i < 2; i++) {
                const int r = r4 + 64 * i;
                float* p = &As[nb][r * 16];
                p[((0 ^ (r & 3)) << 2) + jc] = ra[i].x;
                p[((1 ^ (r & 3)) << 2) + jc] = ra[i].y;
                p[((2 ^ (r & 3)) << 2) + jc] = ra[i].z;
                p[((3 ^ (r & 3)) << 2) + jc] = ra[i].w;
            }
            #pragma unroll
            for (int i = 0; i < 4; i++) {
                const int r = r4 + 64 * i;
                float* p = &Bs[nb][r * 16];
                p[((0 ^ (r & 3)) << 2) + jc] = rb[i].x;
                p[((1 ^ (r & 3)) << 2) + jc] = rb[i].y;
                p[((2 ^ (r & 3)) << 2) + jc] = rb[i].z;
                p[((3 ^ (r & 3)) << 2) + jc] = rb[i].w;
            }
            __syncthreads();
        }
    }

    // -------- epilogue: bias + store --------
    #pragma unroll
    for (int mt = 0; mt < 4; mt++) {
        const int row = bm + wm * 64 + mt * 16 + g;
        #pragma unroll
        for (int nt = 0; nt < 8; nt++) {
            const int col = bn + wn * 64 + nt * 8 + 2 * t4;
            if (col < N) {
                const float bx = __ldg(bias + col), by = __ldg(bias + col + 1);
                float2 v0 = make_float2(acc[mt][nt].x + bx, acc[mt][nt].y + by);
                float2 v1 = make_float2(acc[mt][nt].z + bx, acc[mt][nt].w + by);
                *(float2*)(C + (size_t)row * N + col)       = v0;
                *(float2*)(C + (size_t)(row + 8) * N + col) = v1;
            }
        }
    }
}

// ---------------- tf32 pre-rounding kernel ------------------------
__global__ void cvt_tf32_kernel(const float4* __restrict__ in,
                                float4* __restrict__ out, int n4)
{
    int i = blockIdx.x * blockDim.x + threadIdx.x;
    if (i < n4) {
        float4 v = in[i];
        v.x = to_tf32(v.x); v.y = to_tf32(v.y);
        v.z = to_tf32(v.z); v.w = to_tf32(v.w);
        out[i] = v;
    }
}

// ---------------- Attention kernel (fp32) -------------------------
__global__ __launch_bounds__(256)
void attn_kernel(const float* __restrict__ qkv,
                 const float* __restrict__ freqs,   // [T, 40]
                 float* __restrict__ attout)
{
    extern __shared__ float sh[];
    float* sk = sh;                 // [T][HDIM]
    float* sv = sh + TC * HDIM;     // [T][HDIM]

    const int s   = blockIdx.x;
    const int h   = blockIdx.y;
    const int tid = threadIdx.x;
    const size_t base = (size_t)h * HDIM;

    for (int idx = tid; idx < TC * HDIM; idx += 256) {
        const int t = idx / HDIM, d = idx % HDIM;
        sk[idx] = qkv[(size_t)(t * S1C + s) * QKVD + NECK + base + d];
    }
    __syncthreads();
    for (int idx = tid; idx < TC * (HDIM / 2); idx += 256) {
        const int t = idx / (HDIM / 2), j = idx % (HDIM / 2);
        const float f  = freqs[t * (HDIM / 2) + j];
        const float c  = cosf(f), sn = sinf(f);
        const float x1 = sk[t * HDIM + j];
        const float x2 = sk[t * HDIM + j + HDIM / 2];
        sk[t * HDIM + j]            = x1 * c - x2 * sn;
        sk[t * HDIM + j + HDIM / 2] = x2 * c + x1 * sn;
    }
    __syncthreads();

    for (int idx = tid; idx < TC * HDIM; idx += 256) {
        const int t = idx / HDIM, d = idx % HDIM;
        sv[idx] = qkv[(size_t)(t * S1C + s) * QKVD + base + d];
    }
    __syncthreads();
    for (int idx = tid; idx < TC * (HDIM / 2); idx += 256) {
        const int t = idx / (HDIM / 2), j = idx % (HDIM / 2);
        const float f  = freqs[t * (HDIM / 2) + j];
        const float c  = cosf(f), sn = sinf(f);
        const float x1 = sv[t * HDIM + j];
        const float x2 = sv[t * HDIM + j + HDIM / 2];
        sv[t * HDIM + j]            = x1 * c - x2 * sn;
        sv[t * HDIM + j + HDIM / 2] = x2 * c + x1 * sn;
    }
    __syncthreads();

    float q[HDIM];
    #pragma unroll
    for (int d = 0; d < HDIM; d++) q[d] = sv[tid * HDIM + d];
    __syncthreads();

    for (int idx = tid; idx < TC * HDIM; idx += 256) {
        const int t = idx / HDIM, d = idx % HDIM;
        sv[idx] = qkv[(size_t)(t * S1C + s) * QKVD + 2 * NECK + base + d];
    }
    __syncthreads();

    const float scale = 0.111803398874989484f;   // 1/sqrt(80)

    float m = -1e30f, l = 0.f;
    for (int tk = 0; tk < TC; tk++) {
        const float* kr = sk + tk * HDIM;
        float sdot = 0.f;
        #pragma unroll
        for (int d = 0; d < HDIM; d++) sdot = fmaf(q[d], kr[d], sdot);
        sdot *= scale;
        const float mn = fmaxf(m, sdot);
        l = l * __expf(m - mn) + __expf(sdot - mn);
        m = mn;
    }
    const float rl = 1.f / l;

    float acc[HDIM];
    #pragma unroll
    for (int d = 0; d < HDIM; d++) acc[d] = 0.f;
    for (int tk = 0; tk < TC; tk++) {
        const float* kr = sk + tk * HDIM;
        float sdot = 0.f;
        #pragma unroll
        for (int d = 0; d < HDIM; d++) sdot = fmaf(q[d], kr[d], sdot);
        const float p = __expf(sdot * scale - m) * rl;
        const float* vr = sv + tk * HDIM;
        #pragma unroll
        for (int d = 0; d < HDIM; d++) acc[d] = fmaf(p, vr[d], acc[d]);
    }

    __syncthreads();
    #pragma unroll
    for (int d = 0; d < HDIM; d++) sk[tid * HDIM + d] = acc[d];
    __syncthreads();
    // tf32-rounded store: proj GEMM consumes this directly
    for (int idx = tid; idx < TC * HDIM; idx += 256) {
        const int t = idx / HDIM, d = idx % HDIM;
        attout[(size_t)(s * TC + t) * NECK + base + d] = to_tf32(sk[idx]);
    }
}

// ---------------- Launch -------------------------------------------
extern "C" void kernel_launch(void* const* d_in, const int* in_sizes, int n_in,
                              void* d_out, int out_size)
{
    const float* hidden = (const float*)d_in[0];
    // d_in[1] = cu_seqlens (shapes fixed; unused)
    const float* freqs  = (const float*)d_in[2];
    const float* w_qkv  = (const float*)d_in[3];
    const float* b_qkv  = (const float*)d_in[4];
    const float* w_proj = (const float*)d_in[5];
    const float* b_proj = (const float*)d_in[6];
    float* out = (float*)d_out;

    float *qkv_p, *att_p, *hid_p, *wqkv_p, *wproj_p;
    cudaGetSymbolAddress((void**)&qkv_p,   g_qkv);
    cudaGetSymbolAddress((void**)&att_p,   g_att);
    cudaGetSymbolAddress((void**)&hid_p,   g_hid);
    cudaGetSymbolAddress((void**)&wqkv_p,  g_wqkv);
    cudaGetSymbolAddress((void**)&wproj_p, g_wproj);

    // 0) tf32-round inputs once (removes cvt from GEMM hot loops)
    {
        int n4h = (SEQ * EMBED) / 4;
        cvt_tf32_kernel<<<(n4h + 255) / 256, 256>>>((const float4*)hidden,
                                                    (float4*)hid_p, n4h);
        int n4q = (QKVD * EMBED) / 4;
        cvt_tf32_kernel<<<(n4q + 255) / 256, 256>>>((const float4*)w_qkv,
                                                    (float4*)wqkv_p, n4q);
        int n4p = (EMBED * NECK) / 4;
        cvt_tf32_kernel<<<(n4p + 255) / 256, 256>>>((const float4*)w_proj,
                                                    (float4*)wproj_p, n4p);
    }

    // 1) QKV GEMM: [65536,960] = hid @ w_qkv^T + b_qkv   (K=1280)
    {
        dim3 grid((QKVD + 255) / 256, SEQ / 128);   // 4 x 512
        gemm_tf32_tn_bias<<<grid, 256>>>(hid_p, wqkv_p, b_qkv, qkv_p,
                                         SEQ, QKVD, EMBED);
    }

    // 2) Attention (RoPE fused; emits tf32-rounded att)
    {
        const int smem = 2 * TC * HDIM * (int)sizeof(float);   // 163840
        cudaFuncSetAttribute(attn_kernel,
                             cudaFuncAttributeMaxDynamicSharedMemorySize, smem);
        dim3 grid(S1C, NHEAD);
        attn_kernel<<<grid, 256, smem>>>(qkv_p, freqs, att_p);
    }

    // 3) Proj GEMM: out[65536,1280] = att @ w_proj^T + b_proj  (K=320)
    {
        dim3 grid(EMBED / 256, SEQ / 128);          // 5 x 512
        gemm_tf32_tn_bias<<<grid, 256>>>(att_p, wproj_p, b_proj, out,
                                         SEQ, EMBED, NECK);
    }
}

// round 5
// speedup vs baseline: 3.3345x; 1.4884x over previous
#include <cuda_runtime.h>
#include <cuda_bf16.h>
#include <math.h>
#include <stdint.h>

// ---------------- Problem constants (fixed shapes) ----------------
#define SEQ       65536
#define EMBED     1280
#define NECK      320
#define QKVD      960      // 3 * NECK
#define NHEAD     4
#define HDIM      80
#define S1C       256
#define TC        256

// ---------------- Scratch (alloc-free: __device__ globals) --------
__device__ float g_qkv[(size_t)SEQ * QKVD];     // [t*S1+s, 960]
__device__ float g_att[(size_t)SEQ * NECK];     // [s*T+t, 320] (tf32)
__device__ float g_hid[(size_t)SEQ * EMBED];    // tf32 hidden
__device__ float g_wqkv[(size_t)QKVD * EMBED];  // tf32 w_qkv
__device__ float g_wproj[(size_t)EMBED * NECK]; // tf32 w_proj

// ================= helpers ========================================
__device__ __forceinline__ float to_tf32(float x) {
    uint32_t u;
    asm("cvt.rna.tf32.f32 %0, %1;" : "=r"(u) : "f"(x));
    return __uint_as_float(u);
}

__device__ __forceinline__ void mma_tf32(float4& d,
    float a0, float a1, float a2, float a3, float b0, float b1)
{
    asm volatile(
        "mma.sync.aligned.m16n8k8.row.col.f32.tf32.tf32.f32 "
        "{%0,%1,%2,%3}, {%4,%5,%6,%7}, {%8,%9}, {%0,%1,%2,%3};\n"
        : "+f"(d.x), "+f"(d.y), "+f"(d.z), "+f"(d.w)
        : "r"(__float_as_uint(a0)), "r"(__float_as_uint(a1)),
          "r"(__float_as_uint(a2)), "r"(__float_as_uint(a3)),
          "r"(__float_as_uint(b0)), "r"(__float_as_uint(b1)));
}

// ================= TF32 tensor-core GEMM (unchanged from R4) ======
__global__ __launch_bounds__(256, 1)
void gemm_tf32_tn_bias(const float* __restrict__ A,
                       const float* __restrict__ B,
                       const float* __restrict__ bias,
                       float* __restrict__ C,
                       int M, int N, int K)
{
    __shared__ float As[2][128 * 16];
    __shared__ float Bs[2][256 * 16];

    const int tid  = threadIdx.x;
    const int lane = tid & 31;
    const int warp = tid >> 5;
    const int wm   = warp >> 2;
    const int wn   = warp & 3;
    const int g    = lane >> 2;
    const int t4   = lane & 3;
    const int sw   = ((t4 ^ (g & 3)) << 2);

    const int bm = blockIdx.y * 128;
    const int bn = blockIdx.x * 256;

    const int r4 = tid >> 2;
    const int jc = tid & 3;

    float4 ra[2], rb[4];
    float4 acc[4][8];
    #pragma unroll
    for (int i = 0; i < 4; i++)
        #pragma unroll
        for (int j = 0; j < 8; j++)
            acc[i][j] = make_float4(0.f, 0.f, 0.f, 0.f);

    const int KT = K >> 4;

    #pragma unroll
    for (int i = 0; i < 2; i++)
        ra[i] = *(const float4*)(A + (size_t)(bm + r4 + 64 * i) * K + 4 * jc);
    #pragma unroll
    for (int i = 0; i < 4; i++) {
        const int r = r4 + 64 * i;
        rb[i] = (bn + r < N)
              ? *(const float4*)(B + (size_t)(bn + r) * K + 4 * jc)
              : make_float4(0.f, 0.f, 0.f, 0.f);
    }
    #pragma unroll
    for (int i = 0; i < 2; i++) {
        const int r = r4 + 64 * i;
        float* p = &As[0][r * 16];
        p[((0 ^ (r & 3)) << 2) + jc] = ra[i].x;
        p[((1 ^ (r & 3)) << 2) + jc] = ra[i].y;
        p[((2 ^ (r & 3)) << 2) + jc] = ra[i].z;
        p[((3 ^ (r & 3)) << 2) + jc] = ra[i].w;
    }
    #pragma unroll
    for (int i = 0; i < 4; i++) {
        const int r = r4 + 64 * i;
        float* p = &Bs[0][r * 16];
        p[((0 ^ (r & 3)) << 2) + jc] = rb[i].x;
        p[((1 ^ (r & 3)) << 2) + jc] = rb[i].y;
        p[((2 ^ (r & 3)) << 2) + jc] = rb[i].z;
        p[((3 ^ (r & 3)) << 2) + jc] = rb[i].w;
    }
    __syncthreads();

    for (int kt = 0; kt < KT; kt++) {
        const int buf = kt & 1;

        if (kt + 1 < KT) {
            const int k0 = (kt + 1) << 4;
            #pragma unroll
            for (int i = 0; i < 2; i++)
                ra[i] = *(const float4*)(A + (size_t)(bm + r4 + 64 * i) * K + k0 + 4 * jc);
            #pragma unroll
            for (int i = 0; i < 4; i++) {
                const int r = r4 + 64 * i;
                rb[i] = (bn + r < N)
                      ? *(const float4*)(B + (size_t)(bn + r) * K + k0 + 4 * jc)
                      : make_float4(0.f, 0.f, 0.f, 0.f);
            }
        }

        const float* pa = &As[buf][(wm * 64 + g) * 16 + sw];
        const float* pb = &Bs[buf][(wn * 64 + g) * 16 + sw];

        float4 fb[8];
        #pragma unroll
        for (int nt = 0; nt < 8; nt++)
            fb[nt] = *(const float4*)(pb + nt * 128);

        #pragma unroll
        for (int mt = 0; mt < 4; mt++) {
            const float4 fa  = *(const float4*)(pa + mt * 256);
            const float4 fa2 = *(const float4*)(pa + mt * 256 + 128);
            #pragma unroll
            for (int nt = 0; nt < 8; nt++) {
                mma_tf32(acc[mt][nt], fa.x, fa2.x, fa.y, fa2.y, fb[nt].x, fb[nt].y);
                mma_tf32(acc[mt][nt], fa.z, fa2.z, fa.w, fa2.w, fb[nt].z, fb[nt].w);
            }
        }

        if (kt + 1 < KT) {
            const int nb = buf ^ 1;
            #pragma unroll
            for (int i = 0; i < 2; i++) {
                const int r = r4 + 64 * i;
                float* p = &As[nb][r * 16];
                p[((0 ^ (r & 3)) << 2) + jc] = ra[i].x;
                p[((1 ^ (r & 3)) << 2) + jc] = ra[i].y;
                p[((2 ^ (r & 3)) << 2) + jc] = ra[i].z;
                p[((3 ^ (r & 3)) << 2) + jc] = ra[i].w;
            }
            #pragma unroll
            for (int i = 0; i < 4; i++) {
                const int r = r4 + 64 * i;
                float* p = &Bs[nb][r * 16];
                p[((0 ^ (r & 3)) << 2) + jc] = rb[i].x;
                p[((1 ^ (r & 3)) << 2) + jc] = rb[i].y;
                p[((2 ^ (r & 3)) << 2) + jc] = rb[i].z;
                p[((3 ^ (r & 3)) << 2) + jc] = rb[i].w;
            }
            __syncthreads();
        }
    }

    #pragma unroll
    for (int mt = 0; mt < 4; mt++) {
        const int row = bm + wm * 64 + mt * 16 + g;
        #pragma unroll
        for (int nt = 0; nt < 8; nt++) {
            const int col = bn + wn * 64 + nt * 8 + 2 * t4;
            if (col < N) {
                const float bx = __ldg(bias + col), by = __ldg(bias + col + 1);
                float2 v0 = make_float2(acc[mt][nt].x + bx, acc[mt][nt].y + by);
                float2 v1 = make_float2(acc[mt][nt].z + bx, acc[mt][nt].w + by);
                *(float2*)(C + (size_t)row * N + col)       = v0;
                *(float2*)(C + (size_t)(row + 8) * N + col) = v1;
            }
        }
    }
}

// ---------------- tf32 pre-rounding kernel ------------------------
__global__ void cvt_tf32_kernel(const float4* __restrict__ in,
                                float4* __restrict__ out, int n4)
{
    int i = blockIdx.x * blockDim.x + threadIdx.x;
    if (i < n4) {
        float4 v = in[i];
        v.x = to_tf32(v.x); v.y = to_tf32(v.y);
        v.z = to_tf32(v.z); v.w = to_tf32(v.w);
        out[i] = v;
    }
}

// ---------------- RoPE + tf32 round pass (in place on g_qkv) ------
// One block per seq row (t*S1+s). Rotates Q,K head pairs, rounds Q,K,V.
__global__ __launch_bounds__(128)
void rope_round_kernel(float* __restrict__ qkv,
                       const float* __restrict__ freqs)   // [T,40]
{
    const int row = blockIdx.x;
    const int t   = row >> 8;            // row = t*256 + s
    float* r = qkv + (size_t)row * QKVD;

    __shared__ float cs[40], sn[40];
    if (threadIdx.x < 40) {
        const float f = freqs[t * 40 + threadIdx.x];
        cs[threadIdx.x] = cosf(f);
        sn[threadIdx.x] = sinf(f);
    }
    __syncthreads();

    // Q (sec 0) and K (sec 1): 2 * 4 heads * 40 pairs = 320 items
    for (int i = threadIdx.x; i < 320; i += 128) {
        const int sec = i / 160;         // 0=Q, 1=K
        const int hh  = (i % 160) / 40;
        const int j   = i % 40;
        float* p = r + sec * NECK + hh * HDIM;
        const float x1 = p[j], x2 = p[j + 40];
        p[j]      = to_tf32(x1 * cs[j] - x2 * sn[j]);
        p[j + 40] = to_tf32(x2 * cs[j] + x1 * sn[j]);
    }
    // V: round 320 floats
    for (int i = threadIdx.x; i < NECK; i += 128)
        r[2 * NECK + i] = to_tf32(r[2 * NECK + i]);
}

// ---------------- Tensor-core flash attention ---------------------
// grid (S1, H), 256 threads (8 warps). Each warp: 32 q-rows (2 x m16).
// smem: K [256 r][5 blk*16]  (20480 f)
//       Vt [16 blk][80 r][16] (20480 f)
//       P  [8 warps][4 blk][16 r][16] (8192 f)
#define ATT_SMEM ((20480 + 20480 + 8192) * 4)

#define PADDR(r, ck) ((((ck) >> 4) << 8) + ((r) << 4) + \
                      ((((ck) & 3) ^ ((r) & 3)) << 2) + (((ck) >> 2) & 3))

__global__ __launch_bounds__(256)
void attn_tc_kernel(const float* __restrict__ qkv,
                    float* __restrict__ attout)
{
    extern __shared__ float sh[];
    float* Ks = sh;
    float* Vs = sh + 20480;

    const int s    = blockIdx.x;
    const int h    = blockIdx.y;
    const int tid  = threadIdx.x;
    const int lane = tid & 31;
    const int w    = tid >> 5;
    const int g    = lane >> 2;
    const int t4   = lane & 3;
    const int hb   = h * HDIM;

    // ---- load K (rope'd tf32) into swizzled smem ----
    for (int i = tid; i < TC * HDIM; i += 256) {
        const int t = i / HDIM, d = i % HDIM;
        const float v = qkv[(size_t)(t * S1C + s) * QKVD + NECK + hb + d];
        Ks[t * 80 + ((d >> 4) << 4) + (((d & 3) ^ (t & 3)) << 2) + ((d >> 2) & 3)] = v;
    }
    // ---- load V transposed into swizzled smem ----
    for (int i = tid; i < TC * HDIM; i += 256) {
        const int t = i / HDIM, d = i % HDIM;
        const float v = qkv[(size_t)(t * S1C + s) * QKVD + 2 * NECK + hb + d];
        Vs[(t >> 4) * 1280 + (d << 4) + (((t & 3) ^ (d & 3)) << 2) + ((t >> 2) & 3)] = v;
    }
    __syncthreads();

    float* Pw = sh + 40960 + w * 1024;
    const float scale = 0.111803398874989484f;   // 1/sqrt(80)
    const int swg = ((t4 ^ (g & 3)) << 2);

    #pragma unroll
    for (int rg = 0; rg < 2; rg++) {
        const int R0 = w * 32 + rg * 16;

        // ---- Q fragments from global (rope'd tf32) ----
        float4 qa[5], qb[5];
        {
            const float* p0 = qkv + (size_t)((R0 + g) * S1C + s) * QKVD + hb + t4;
            const float* p1 = qkv + (size_t)((R0 + g + 8) * S1C + s) * QKVD + hb + t4;
            #pragma unroll
            for (int b = 0; b < 5; b++) {
                qa[b] = make_float4(p0[b*16], p0[b*16+4], p0[b*16+8], p0[b*16+12]);
                qb[b] = make_float4(p1[b*16], p1[b*16+4], p1[b*16+8], p1[b*16+12]);
            }
        }

        float m0 = -1e30f, m1 = -1e30f, l0 = 0.f, l1 = 0.f;
        float4 o[10];
        #pragma unroll
        for (int dt = 0; dt < 10; dt++) o[dt] = make_float4(0.f, 0.f, 0.f, 0.f);

        for (int c = 0; c < 4; c++) {
            // ---- S = Q @ K^T for this 64-key chunk ----
            float4 sacc[8];
            #pragma unroll
            for (int nt = 0; nt < 8; nt++) sacc[nt] = make_float4(0.f, 0.f, 0.f, 0.f);
            #pragma unroll
            for (int nt = 0; nt < 8; nt++) {
                const int krow = c * 64 + nt * 8 + g;
                const float* pb = Ks + krow * 80 + swg;   // krow&3 == g&3
                #pragma unroll
                for (int b = 0; b < 5; b++) {
                    const float4 fb = *(const float4*)(pb + b * 16);
                    mma_tf32(sacc[nt], qa[b].x, qb[b].x, qa[b].y, qb[b].y, fb.x, fb.y);
                    mma_tf32(sacc[nt], qa[b].z, qb[b].z, qa[b].w, qb[b].w, fb.z, fb.w);
                }
            }

            // ---- online softmax (rows g / g+8) ----
            float mx0 = -1e30f, mx1 = -1e30f;
            #pragma unroll
            for (int nt = 0; nt < 8; nt++) {
                sacc[nt].x *= scale; sacc[nt].y *= scale;
                sacc[nt].z *= scale; sacc[nt].w *= scale;
                mx0 = fmaxf(mx0, fmaxf(sacc[nt].x, sacc[nt].y));
                mx1 = fmaxf(mx1, fmaxf(sacc[nt].z, sacc[nt].w));
            }
            mx0 = fmaxf(mx0, __shfl_xor_sync(0xffffffffu, mx0, 1));
            mx0 = fmaxf(mx0, __shfl_xor_sync(0xffffffffu, mx0, 2));
            mx1 = fmaxf(mx1, __shfl_xor_sync(0xffffffffu, mx1, 1));
            mx1 = fmaxf(mx1, __shfl_xor_sync(0xffffffffu, mx1, 2));

            const float mn0 = fmaxf(m0, mx0), mn1 = fmaxf(m1, mx1);
            const float cor0 = __expf(m0 - mn0), cor1 = __expf(m1 - mn1);

            float s0 = 0.f, s1 = 0.f;
            #pragma unroll
            for (int nt = 0; nt < 8; nt++) {
                sacc[nt].x = __expf(sacc[nt].x - mn0); s0 += sacc[nt].x;
                sacc[nt].y = __expf(sacc[nt].y - mn0); s0 += sacc[nt].y;
                sacc[nt].z = __expf(sacc[nt].z - mn1); s1 += sacc[nt].z;
                sacc[nt].w = __expf(sacc[nt].w - mn1); s1 += sacc[nt].w;
            }
            s0 += __shfl_xor_sync(0xffffffffu, s0, 1);
            s0 += __shfl_xor_sync(0xffffffffu, s0, 2);
            s1 += __shfl_xor_sync(0xffffffffu, s1, 1);
            s1 += __shfl_xor_sync(0xffffffffu, s1, 2);

            l0 = l0 * cor0 + s0;  l1 = l1 * cor1 + s1;
            m0 = mn0;             m1 = mn1;

            #pragma unroll
            for (int dt = 0; dt < 10; dt++) {
                o[dt].x *= cor0; o[dt].y *= cor0;
                o[dt].z *= cor1; o[dt].w *= cor1;
            }

            // ---- P -> per-warp smem slab (tf32) ----
            __syncwarp();
            #pragma unroll
            for (int nt = 0; nt < 8; nt++) {
                const int ck0 = nt * 8 + 2 * t4;
                Pw[PADDR(g,     ck0    )] = to_tf32(sacc[nt].x);
                Pw[PADDR(g,     ck0 + 1)] = to_tf32(sacc[nt].y);
                Pw[PADDR(g + 8, ck0    )] = to_tf32(sacc[nt].z);
                Pw[PADDR(g + 8, ck0 + 1)] = to_tf32(sacc[nt].w);
            }
            __syncwarp();

            // ---- P fragments + O += P @ V ----
            float4 pa[4], pc[4];
            #pragma unroll
            for (int kb = 0; kb < 4; kb++) {
                const float* pp = Pw + kb * 256 + g * 16 + swg;
                pa[kb] = *(const float4*)(pp);
                pc[kb] = *(const float4*)(pp + 128);     // row g+8
            }
            #pragma unroll
            for (int dt = 0; dt < 10; dt++) {
                const int drow = dt * 8 + g;
                const float* pv = Vs + (c * 4) * 1280 + drow * 16 + swg; // drow&3==g&3
                #pragma unroll
                for (int kb = 0; kb < 4; kb++) {
                    const float4 fv = *(const float4*)(pv + kb * 1280);
                    mma_tf32(o[dt], pa[kb].x, pc[kb].x, pa[kb].y, pc[kb].y, fv.x, fv.y);
                    mma_tf32(o[dt], pa[kb].z, pc[kb].z, pa[kb].w, pc[kb].w, fv.z, fv.w);
                }
            }
        }

        // ---- epilogue: O/l, tf32 store ----
        const float il0 = 1.f / l0, il1 = 1.f / l1;
        const int col = hb + 2 * t4;
        #pragma unroll
        for (int dt = 0; dt < 10; dt++) {
            float2 v0 = make_float2(to_tf32(o[dt].x * il0), to_tf32(o[dt].y * il0));
            float2 v1 = make_float2(to_tf32(o[dt].z * il1), to_tf32(o[dt].w * il1));
            *(float2*)(attout + (size_t)(s * TC + R0 + g)     * NECK + col + dt * 8) = v0;
            *(float2*)(attout + (size_t)(s * TC + R0 + g + 8) * NECK + col + dt * 8) = v1;
        }
    }
}

// ---------------- Launch -------------------------------------------
extern "C" void kernel_launch(void* const* d_in, const int* in_sizes, int n_in,
                              void* d_out, int out_size)
{
    const float* hidden = (const float*)d_in[0];
    const float* freqs  = (const float*)d_in[2];
    const float* w_qkv  = (const float*)d_in[3];
    const float* b_qkv  = (const float*)d_in[4];
    const float* w_proj = (const float*)d_in[5];
    const float* b_proj = (const float*)d_in[6];
    float* out = (float*)d_out;

    float *qkv_p, *att_p, *hid_p, *wqkv_p, *wproj_p;
    cudaGetSymbolAddress((void**)&qkv_p,   g_qkv);
    cudaGetSymbolAddress((void**)&att_p,   g_att);
    cudaGetSymbolAddress((void**)&hid_p,   g_hid);
    cudaGetSymbolAddress((void**)&wqkv_p,  g_wqkv);
    cudaGetSymbolAddress((void**)&wproj_p, g_wproj);

    // 0) tf32-round inputs once
    {
        int n4h = (SEQ * EMBED) / 4;
        cvt_tf32_kernel<<<(n4h + 255) / 256, 256>>>((const float4*)hidden,
                                                    (float4*)hid_p, n4h);
        int n4q = (QKVD * EMBED) / 4;
        cvt_tf32_kernel<<<(n4q + 255) / 256, 256>>>((const float4*)w_qkv,
                                                    (float4*)wqkv_p, n4q);
        int n4p = (EMBED * NECK) / 4;
        cvt_tf32_kernel<<<(n4p + 255) / 256, 256>>>((const float4*)w_proj,
                                                    (float4*)wproj_p, n4p);
    }

    // 1) QKV GEMM: [65536,960] = hid @ w_qkv^T + b_qkv   (K=1280)
    {
        dim3 grid((QKVD + 255) / 256, SEQ / 128);
        gemm_tf32_tn_bias<<<grid, 256>>>(hid_p, wqkv_p, b_qkv, qkv_p,
                                         SEQ, QKVD, EMBED);
    }

    // 1.5) RoPE + tf32 round (in place on g_qkv)
    rope_round_kernel<<<SEQ, 128>>>(qkv_p, freqs);

    // 2) Tensor-core attention -> g_att (tf32)
    {
        cudaFuncSetAttribute(attn_tc_kernel,
                             cudaFuncAttributeMaxDynamicSharedMemorySize, ATT_SMEM);
        dim3 grid(S1C, NHEAD);
        attn_tc_kernel<<<grid, 256, ATT_SMEM>>>(qkv_p, att_p);
    }

    // 3) Proj GEMM: out[65536,1280] = att @ w_proj^T + b_proj  (K=320)
    {
        dim3 grid(EMBED / 256, SEQ / 128);
        gemm_tf32_tn_bias<<<grid, 256>>>(att_p, wproj_p, b_proj, out,
                                         SEQ, EMBED, NECK);
    }
}